// round 2
// baseline (speedup 1.0000x reference)
#include <cuda_runtime.h>
#include <cstdint>

#define EPSF 1e-5f
#define MAX_N 524288  // capacity for rows of h (N = 500000 in this problem)

// Scratch (allocation-free): per-row alpha = max(1 - ||h_i||^2, EPS), and accumulators.
__device__ float  g_alpha[MAX_N];
__device__ double g_acc[3];   // [0]=sum softplus(pos), [1]=sum softplus(-neg), [2]=sum 1/(rank+1)

__global__ void hat_init_acc() {
    if (threadIdx.x < 3) g_acc[threadIdx.x] = 0.0;
}

// One warp per row: coalesced float2 read of 64 floats, 5-level xor reduce.
__global__ void hat_alpha_kernel(const float* __restrict__ h, int N) {
    int warp = (blockIdx.x * blockDim.x + threadIdx.x) >> 5;
    int lane = threadIdx.x & 31;
    if (warp >= N) return;
    float2 u = reinterpret_cast<const float2*>(h)[(warp << 5) + lane];
    float s = u.x * u.x + u.y * u.y;
    #pragma unroll
    for (int o = 16; o; o >>= 1) s += __shfl_xor_sync(0xFFFFFFFFu, s, o);
    if (lane == 0) g_alpha[warp] = fmaxf(1.0f - s, EPSF);
}

__device__ __forceinline__ float softplusf(float x) {
    // softplus(x) = max(x,0) + log1p(exp(-|x|))
    return fmaxf(x, 0.0f) + log1pf(__expf(-fabsf(x)));
}

// Warp per pos-edge group (1 pos + neg_nums negs). Persistent grid-stride.
__global__ void __launch_bounds__(256) hat_main_kernel(
    const float* __restrict__ h,
    const int*   __restrict__ pos_src, const int* __restrict__ pos_dst,
    const int*   __restrict__ neg_src, const int* __restrict__ neg_dst,
    int E_pos, int neg_nums)
{
    const int lane        = threadIdx.x & 31;
    const int warp_global = (blockIdx.x * blockDim.x + threadIdx.x) >> 5;
    const int nwarps      = (gridDim.x * blockDim.x) >> 5;

    float acc_pos = 0.0f;   // lane 0 accumulates softplus(pos)
    float acc_neg = 0.0f;   // lanes 1..neg_nums accumulate softplus(-neg)
    float acc_mrr = 0.0f;   // lane 0 accumulates 1/(rank+1)

    for (int i = warp_global; i < E_pos; i += nwarps) {
        // Lane e in [0, neg_nums] owns edge e of this group: lane 0 = positive,
        // lanes 1..neg_nums = negatives. Load all indices in parallel.
        int s_idx = 0, d_idx = 0;
        if (lane == 0)              { s_idx = pos_src[i];  d_idx = pos_dst[i]; }
        else if (lane <= neg_nums)  { int b = i * neg_nums + lane - 1;
                                      s_idx = neg_src[b];  d_idx = neg_dst[b]; }

        float my_ab = 1.0f;
        if (lane <= neg_nums) my_ab = g_alpha[s_idx] * g_alpha[d_idx];

        float my_sq = 0.0f;
        #pragma unroll 6
        for (int e = 0; e <= neg_nums; e++) {
            int s = __shfl_sync(0xFFFFFFFFu, s_idx, e);
            int d = __shfl_sync(0xFFFFFFFFu, d_idx, e);
            float2 u = reinterpret_cast<const float2*>(h)[(s << 5) + lane];
            float2 v = reinterpret_cast<const float2*>(h)[(d << 5) + lane];
            float dx = u.x - v.x, dy = u.y - v.y;
            float sq = fmaf(dx, dx, dy * dy);
            #pragma unroll
            for (int o = 16; o; o >>= 1) sq += __shfl_xor_sync(0xFFFFFFFFu, sq, o);
            if (lane == e) my_sq = sq;
        }

        // Lanes 0..neg_nums compute their edge's Poincare dist^2 in parallel.
        float score = 0.0f;
        if (lane <= neg_nums) {
            float x = fmaxf(2.0f * my_sq / my_ab, EPSF);           // gamma - 1
            float dd = log1pf(x + sqrtf(x * (x + 2.0f)));          // arccosh(1+x)
            score = dd * dd;
        }
        float pos_score = __shfl_sync(0xFFFFFFFFu, score, 0);

        // rank = #{neg: -neg_score > -pos_score} = #{neg: neg_score < pos_score}
        unsigned lt = __ballot_sync(0xFFFFFFFFu,
                                    (lane >= 1) && (lane <= neg_nums) && (score < pos_score));
        int rank = __popc(lt);

        if (lane == 0) {
            acc_pos += softplusf(pos_score);
            acc_mrr += 1.0f / (float)(rank + 1);
        } else if (lane <= neg_nums) {
            acc_neg += softplusf(-score);
        }
    }

    // Reduce acc_neg across the warp (pos/mrr already live on lane 0 only).
    #pragma unroll
    for (int o = 16; o; o >>= 1) acc_neg += __shfl_xor_sync(0xFFFFFFFFu, acc_neg, o);

    __shared__ float s_pos[8], s_neg[8], s_mrr[8];
    int wid = threadIdx.x >> 5;
    if (lane == 0) { s_pos[wid] = acc_pos; s_neg[wid] = acc_neg; s_mrr[wid] = acc_mrr; }
    __syncthreads();
    if (threadIdx.x == 0) {
        double p = 0.0, n = 0.0, m = 0.0;
        int nw = blockDim.x >> 5;
        for (int w = 0; w < nw; w++) { p += s_pos[w]; n += s_neg[w]; m += s_mrr[w]; }
        atomicAdd(&g_acc[0], p);
        atomicAdd(&g_acc[1], n);
        atomicAdd(&g_acc[2], m);
    }
}

__global__ void hat_finalize(float* __restrict__ out, int E_pos, int E_neg, int out_size) {
    if (threadIdx.x == 0 && blockIdx.x == 0) {
        float loss = (float)(g_acc[0] / (double)E_pos + g_acc[1] / (double)E_neg);
        float mrr  = (float)(g_acc[2] / (double)E_pos);
        out[0] = loss;
        if (out_size > 1) out[1] = mrr;
    }
}

extern "C" void kernel_launch(void* const* d_in, const int* in_sizes, int n_in,
                              void* d_out, int out_size)
{
    const float* h       = (const float*)d_in[0];
    const int*   pos_src = (const int*)d_in[1];
    const int*   pos_dst = (const int*)d_in[2];
    const int*   neg_src = (const int*)d_in[3];
    const int*   neg_dst = (const int*)d_in[4];

    int h_elems = in_sizes[0];
    int E_pos   = in_sizes[1];
    int E_neg   = in_sizes[3];
    int N       = h_elems / 64;
    int neg_nums = (E_pos > 0) ? (E_neg / E_pos) : 1;

    float* out = (float*)d_out;

    hat_init_acc<<<1, 32>>>();

    // alpha precompute: one warp per row
    {
        int threads = 256;
        int blocks  = (N * 32 + threads - 1) / threads;
        hat_alpha_kernel<<<blocks, threads>>>(h, N);
    }

    // main: persistent grid-stride, warp per edge-group
    {
        int threads = 256;
        int blocks  = 148 * 8;   // grid-stride handles any SM count / wave split
        hat_main_kernel<<<blocks, threads>>>(h, pos_src, pos_dst, neg_src, neg_dst,
                                             E_pos, neg_nums);
    }

    hat_finalize<<<1, 32>>>(out, E_pos, E_neg, out_size);
}